// round 11
// baseline (speedup 1.0000x reference)
#include <cuda_runtime.h>
#include <cuda_bf16.h>
#include <cstdint>
#include <math.h>

#define T_LEN 512
#define B_SZ  128
#define D_IN  256
#define U_SZ  256
#define NG    768
#define WHS 260              // Wh_s column stride
#define HSS 260              // h_s row stride (plus per-row skew)
#define BG_CTAS 32           // CTAs per batch-group barrier
// skewed row base: rows 4 apart land on distinct bank-quads
#define HROW(r) ((r) * HSS + (((r) >> 2) << 2))

// ---------------- scratch ----------------
__device__ float    g_x [T_LEN * B_SZ * U_SZ];
__device__ float    g_xp[T_LEN * B_SZ * NG];
__device__ unsigned g_bar[4 * T_LEN * 4];        // [layer][t][bg]

// ---------------- embedding ----------------
__global__ void embed_kernel(const int* __restrict__ tokens, const float* __restrict__ emb) {
    int gid = blockIdx.x * blockDim.x + threadIdx.x;
    int row = gid >> 6;
    int c4  = gid & 63;
    int t = row >> 7;
    int b = row & 127;
    int tok = tokens[b * T_LEN + t];
    const float4* e4 = reinterpret_cast<const float4*>(emb);
    float4*       x4 = reinterpret_cast<float4*>(g_x);
    x4[(size_t)row * 64 + c4] = e4[(size_t)tok * 64 + c4];
}

// ---------------- input projection GEMM (unchanged from 9120us kernel) ----------------
__global__ __launch_bounds__(256) void proj_kernel(const float* __restrict__ W,
                                                   const float* __restrict__ bias) {
    __shared__ float As[16][128];
    __shared__ float Bs[16][128];
    int m0 = blockIdx.x * 128;
    int n0 = blockIdx.y * 128;
    int tid = threadIdx.x;
    int tx = tid & 15, ty = tid >> 4;
    float acc[8][8] = {};

    for (int k0 = 0; k0 < 256; k0 += 16) {
        #pragma unroll
        for (int i = 0; i < 2; i++) {               // A tile: transposed store
            int fid = tid + i * 256;
            int m   = fid >> 2;
            int kv  = fid & 3;
            float4 v = *reinterpret_cast<const float4*>(
                &g_x[(size_t)(m0 + m) * 256 + k0 + kv * 4]);
            As[kv * 4 + 0][m] = v.x; As[kv * 4 + 1][m] = v.y;
            As[kv * 4 + 2][m] = v.z; As[kv * 4 + 3][m] = v.w;
        }
        #pragma unroll
        for (int i = 0; i < 2; i++) {               // B tile: direct copy
            int fid = tid + i * 256;
            int kr  = fid >> 5;
            int nc  = fid & 31;
            *reinterpret_cast<float4*>(&Bs[kr][nc * 4]) =
                *reinterpret_cast<const float4*>(&W[(size_t)(k0 + kr) * NG + n0 + nc * 4]);
        }
        __syncthreads();
        #pragma unroll
        for (int kk = 0; kk < 16; kk++) {
            float4 b0 = *reinterpret_cast<const float4*>(&Bs[kk][tx * 4]);
            float4 b1 = *reinterpret_cast<const float4*>(&Bs[kk][64 + tx * 4]);
            float a[8];
            #pragma unroll
            for (int i = 0; i < 8; i++) a[i] = As[kk][ty * 8 + i];
            #pragma unroll
            for (int i = 0; i < 8; i++) {
                acc[i][0] = fmaf(a[i], b0.x, acc[i][0]);
                acc[i][1] = fmaf(a[i], b0.y, acc[i][1]);
                acc[i][2] = fmaf(a[i], b0.z, acc[i][2]);
                acc[i][3] = fmaf(a[i], b0.w, acc[i][3]);
                acc[i][4] = fmaf(a[i], b1.x, acc[i][4]);
                acc[i][5] = fmaf(a[i], b1.y, acc[i][5]);
                acc[i][6] = fmaf(a[i], b1.z, acc[i][6]);
                acc[i][7] = fmaf(a[i], b1.w, acc[i][7]);
            }
        }
        __syncthreads();
    }
    {
        int nA = n0 + tx * 4;
        int nB = n0 + 64 + tx * 4;
        float4 biasA = *reinterpret_cast<const float4*>(&bias[nA]);
        float4 biasB = *reinterpret_cast<const float4*>(&bias[nB]);
        #pragma unroll
        for (int i = 0; i < 8; i++) {
            size_t m = (size_t)(m0 + ty * 8 + i);
            float4 oA = make_float4(acc[i][0] + biasA.x, acc[i][1] + biasA.y,
                                    acc[i][2] + biasA.z, acc[i][3] + biasA.w);
            float4 oB = make_float4(acc[i][4] + biasB.x, acc[i][5] + biasB.y,
                                    acc[i][6] + biasB.z, acc[i][7] + biasB.w);
            *reinterpret_cast<float4*>(&g_xp[m * NG + nA]) = oA;
            *reinterpret_cast<float4*>(&g_xp[m * NG + nB]) = oB;
        }
    }
}

// ---------------- recurrent scan (9120us structure + skewed h_s + g_h removed) ----------------
// grid (32, 4): blockIdx.x = column-group (8 hidden units), blockIdx.y = batch-group (32 rows).
// GEMM phase: 256 threads = 64 positions (8 row-groups x 8 units) x 4 K-slices.
// h exchange through g_x[t] itself (single store), per-bg 32-CTA counter barrier.
extern __shared__ float smem[];
__global__ __launch_bounds__(256) void scan_kernel(const float* __restrict__ Wh,
                                                   const float* __restrict__ bh,
                                                   int layer) {
    float* Wh_s = smem;                            // [24 cols][WHS], col = gate*8 + j
    float* h_s  = smem + 24 * WHS;                 // skewed [32 rows], HROW(r) base
    float* red  = smem + 24 * WHS + 32 * HSS + 32; // [4 ks][64 p][12]
    int cg = blockIdx.x;
    int bg = blockIdx.y;
    int tid = threadIdx.x;
    int u0 = cg * 8;
    int b0 = bg * 32;
    unsigned* bar = g_bar + (layer * T_LEN) * 4 + bg;

    // GEMM-phase decode
    int ks  = tid >> 6;            // 0..3  K-slice
    int pos = tid & 63;            // 0..63
    int ty2 = pos >> 3;            // row-group 0..7 (rows ty2*4..+3)
    int txg = pos & 7;             // unit 0..7

    // Epilogue decode
    int er = tid >> 3;             // row 0..31
    int ej = tid & 7;              // unit 0..7
    int ep = (er >> 2) * 8 + ej;
    int erp = er & 3;

    // one-time Wh slice load
    for (int idx = tid; idx < 24 * 256; idx += 256) {
        int col  = idx >> 8;
        int k    = idx & 255;
        int gate = col >> 3;
        int j    = col & 7;
        Wh_s[col * WHS + k] = Wh[(size_t)k * NG + gate * 256 + u0 + j];
    }
    for (int i = tid; i < 32 * HSS + 32; i += 256) h_s[i] = 0.f;

    float bhz = bh[0 * 256 + u0 + ej];
    float bhr = bh[1 * 256 + u0 + ej];
    float bhh = bh[2 * 256 + u0 + ej];

    const float4* wz4 = reinterpret_cast<const float4*>(&Wh_s[(0 * 8 + txg) * WHS + ks * 64]);
    const float4* wr4 = reinterpret_cast<const float4*>(&Wh_s[(1 * 8 + txg) * WHS + ks * 64]);
    const float4* wh4 = reinterpret_cast<const float4*>(&Wh_s[(2 * 8 + txg) * WHS + ks * 64]);
    const float4* h0_4 = reinterpret_cast<const float4*>(h_s + HROW(ty2 * 4 + 0)) + ks * 16;
    const float4* h1_4 = reinterpret_cast<const float4*>(h_s + HROW(ty2 * 4 + 1)) + ks * 16;
    const float4* h2_4 = reinterpret_cast<const float4*>(h_s + HROW(ty2 * 4 + 2)) + ks * 16;
    const float4* h3_4 = reinterpret_cast<const float4*>(h_s + HROW(ty2 * 4 + 3)) + ks * 16;
    float* myred = &red[(ks * 64 + pos) * 12];

    int bglob = b0 + er;
    int u = u0 + ej;
    float hprev = 0.f;

    // prologue: xp(t=0)
    size_t xb0 = (size_t)bglob * NG;
    float xz = __ldcs(&g_xp[xb0 + u]);
    float xr = __ldcs(&g_xp[xb0 + 256 + u]);
    float xh = __ldcs(&g_xp[xb0 + 512 + u]);
    __syncthreads();

    for (int t = 0; t < T_LEN; t++) {
        // prefetch xp(t+1)
        float nxz = 0.f, nxr = 0.f, nxh = 0.f;
        if (t + 1 < T_LEN) {
            size_t xb = ((size_t)(t + 1) * B_SZ + bglob) * NG;
            nxz = __ldcs(&g_xp[xb + u]);
            nxr = __ldcs(&g_xp[xb + 256 + u]);
            nxh = __ldcs(&g_xp[xb + 512 + u]);
        }

        // ---- GEMM phase: acc[4 rows][3 gates] over K-slice of 64 ----
        float az0=0,az1=0,az2=0,az3=0, ar0=0,ar1=0,ar2=0,ar3=0, ah0=0,ah1=0,ah2=0,ah3=0;
        #pragma unroll 4
        for (int k4 = 0; k4 < 16; k4++) {
            float4 w_z = wz4[k4], w_r = wr4[k4], w_h = wh4[k4];
            float4 v0 = h0_4[k4], v1 = h1_4[k4], v2 = h2_4[k4], v3 = h3_4[k4];
            az0 = fmaf(v0.x,w_z.x,az0); az0 = fmaf(v0.y,w_z.y,az0); az0 = fmaf(v0.z,w_z.z,az0); az0 = fmaf(v0.w,w_z.w,az0);
            az1 = fmaf(v1.x,w_z.x,az1); az1 = fmaf(v1.y,w_z.y,az1); az1 = fmaf(v1.z,w_z.z,az1); az1 = fmaf(v1.w,w_z.w,az1);
            az2 = fmaf(v2.x,w_z.x,az2); az2 = fmaf(v2.y,w_z.y,az2); az2 = fmaf(v2.z,w_z.z,az2); az2 = fmaf(v2.w,w_z.w,az2);
            az3 = fmaf(v3.x,w_z.x,az3); az3 = fmaf(v3.y,w_z.y,az3); az3 = fmaf(v3.z,w_z.z,az3); az3 = fmaf(v3.w,w_z.w,az3);
            ar0 = fmaf(v0.x,w_r.x,ar0); ar0 = fmaf(v0.y,w_r.y,ar0); ar0 = fmaf(v0.z,w_r.z,ar0); ar0 = fmaf(v0.w,w_r.w,ar0);
            ar1 = fmaf(v1.x,w_r.x,ar1); ar1 = fmaf(v1.y,w_r.y,ar1); ar1 = fmaf(v1.z,w_r.z,ar1); ar1 = fmaf(v1.w,w_r.w,ar1);
            ar2 = fmaf(v2.x,w_r.x,ar2); ar2 = fmaf(v2.y,w_r.y,ar2); ar2 = fmaf(v2.z,w_r.z,ar2); ar2 = fmaf(v2.w,w_r.w,ar2);
            ar3 = fmaf(v3.x,w_r.x,ar3); ar3 = fmaf(v3.y,w_r.y,ar3); ar3 = fmaf(v3.z,w_r.z,ar3); ar3 = fmaf(v3.w,w_r.w,ar3);
            ah0 = fmaf(v0.x,w_h.x,ah0); ah0 = fmaf(v0.y,w_h.y,ah0); ah0 = fmaf(v0.z,w_h.z,ah0); ah0 = fmaf(v0.w,w_h.w,ah0);
            ah1 = fmaf(v1.x,w_h.x,ah1); ah1 = fmaf(v1.y,w_h.y,ah1); ah1 = fmaf(v1.z,w_h.z,ah1); ah1 = fmaf(v1.w,w_h.w,ah1);
            ah2 = fmaf(v2.x,w_h.x,ah2); ah2 = fmaf(v2.y,w_h.y,ah2); ah2 = fmaf(v2.z,w_h.z,ah2); ah2 = fmaf(v2.w,w_h.w,ah2);
            ah3 = fmaf(v3.x,w_h.x,ah3); ah3 = fmaf(v3.y,w_h.y,ah3); ah3 = fmaf(v3.z,w_h.z,ah3); ah3 = fmaf(v3.w,w_h.w,ah3);
        }
        {
            float4 s0 = make_float4(az0, ar0, ah0, az1);
            float4 s1 = make_float4(ar1, ah1, az2, ar2);
            float4 s2 = make_float4(ah2, az3, ar3, ah3);
            float4* r4 = reinterpret_cast<float4*>(myred);
            r4[0] = s0; r4[1] = s1; r4[2] = s2;
        }
        __syncthreads();

        // ---- epilogue ----
        float az = bhz, ar = bhr, ah = bhh;
        #pragma unroll
        for (int s = 0; s < 4; s++) {
            const float* rr = &red[(s * 64 + ep) * 12 + erp * 3];
            az += rr[0]; ar += rr[1]; ah += rr[2];
        }

        float z  = __fdividef(1.f, 1.f + __expf(-(xz + az)));
        float r  = __fdividef(1.f, 1.f + __expf(-(xr + ar)));
        float e2 = __expf(2.f * (xh + r * ah));
        float cand = 1.f - __fdividef(2.f, e2 + 1.f);     // tanh
        float hn = z * hprev + (1.f - z) * cand;
        hprev = hn;

        __syncthreads();   // red reads done (before release & before reuse next t)

        if (t < T_LEN - 1) {
            if (tid == 0) {
                __stcg(&g_x[((size_t)t * B_SZ + bglob) * 256 + u], hn);
                unsigned* a = &bar[t * 4];
                asm volatile("red.release.gpu.global.add.u32 [%0], %1;"
                             :: "l"(a), "r"(1u) : "memory");
                unsigned v;
                do {
                    asm volatile("ld.acquire.gpu.global.u32 %0, [%1];"
                                 : "=r"(v) : "l"(a) : "memory");
                } while (v < BG_CTAS);
            } else {
                __stcg(&g_x[((size_t)t * B_SZ + bglob) * 256 + u], hn);  // overlap with spin
            }
            __syncthreads();
            // reload 32x256 h tile from g_x[t] (L2) into skewed h_s
            const float4* hg = reinterpret_cast<const float4*>(&g_x[((size_t)t * B_SZ + b0) * 256]);
            #pragma unroll
            for (int i = 0; i < 8; i++) {
                int idx = tid + i * 256;
                float4 v = __ldcg(&hg[idx]);
                int row = idx >> 6, c4 = idx & 63;
                reinterpret_cast<float4*>(h_s + HROW(row))[c4] = v;
            }
            __syncthreads();
        } else {
            __stcg(&g_x[((size_t)t * B_SZ + bglob) * 256 + u], hn);
        }
        xz = nxz; xr = nxr; xh = nxh;
    }
}

// ---------------- classifier head ----------------
__global__ void dense_kernel(const float* __restrict__ Wd1, const float* __restrict__ bd1,
                             const float* __restrict__ Wd2, const float* __restrict__ bd2,
                             float* __restrict__ out) {
    __shared__ float xs[256];
    __shared__ float red[256];
    int b = blockIdx.x;
    int j = threadIdx.x;
    xs[j] = g_x[((size_t)(T_LEN - 1) * B_SZ + b) * 256 + j];
    __syncthreads();
    float acc = bd1[j];
    #pragma unroll 8
    for (int k = 0; k < 256; k++) acc = fmaf(xs[k], Wd1[k * 256 + j], acc);
    float h1 = acc > 0.f ? acc : 0.f;
    red[j] = h1 * Wd2[j];
    __syncthreads();
    for (int s = 128; s > 0; s >>= 1) {
        if (j < s) red[j] += red[j + s];
        __syncthreads();
    }
    if (j == 0) out[b] = 1.f / (1.f + expf(-(red[0] + bd2[0])));
}

// ---------------- launch ----------------
extern "C" void kernel_launch(void* const* d_in, const int* in_sizes, int n_in,
                              void* d_out, int out_size) {
    const int*   tokens = (const int*)  d_in[0];
    const float* emb    = (const float*)d_in[1];
    float* out = (float*)d_out;

    void* bar_addr; cudaGetSymbolAddress(&bar_addr, g_bar);

    const int scan_smem = (24 * WHS + 32 * HSS + 32 + 4 * 64 * 12) * (int)sizeof(float); // 70656 B
    cudaFuncSetAttribute(scan_kernel, cudaFuncAttributeMaxDynamicSharedMemorySize, scan_smem);

    cudaMemsetAsync(bar_addr, 0, sizeof(unsigned) * 4 * T_LEN * 4);

    embed_kernel<<<16384, 256>>>(tokens, emb);

    for (int l = 0; l < 4; l++) {
        const float* Wx = (const float*)d_in[2 + 4 * l];
        const float* Wh = (const float*)d_in[3 + 4 * l];
        const float* bx = (const float*)d_in[4 + 4 * l];
        const float* bh = (const float*)d_in[5 + 4 * l];

        dim3 pgrid(512, 6);
        proj_kernel<<<pgrid, 256>>>(Wx, bx);

        scan_kernel<<<dim3(32, 4), 256, scan_smem>>>(Wh, bh, l);
    }

    dense_kernel<<<128, 256>>>((const float*)d_in[18], (const float*)d_in[19],
                               (const float*)d_in[20], (const float*)d_in[21], out);
}

// round 12
// speedup vs baseline: 1.0622x; 1.0622x over previous
#include <cuda_runtime.h>
#include <cuda_bf16.h>
#include <cstdint>
#include <math.h>

#define T_LEN 512
#define B_SZ  128
#define D_IN  256
#define U_SZ  256
#define NG    768
#define WHS 260              // Wh_s column stride
#define HSS 260              // h_s row stride (plus per-row skew)
#define BG_CTAS 32           // CTAs per batch-group barrier
// skewed row base: rows 4 apart land on distinct bank-quads
#define HROW(r) ((r) * HSS + (((r) >> 2) << 2))

// ---------------- scratch ----------------
__device__ float    g_x [T_LEN * B_SZ * U_SZ];
__device__ float    g_xp[T_LEN * B_SZ * NG];
__device__ unsigned g_bar[4 * T_LEN * 4];        // [layer][t][bg]

// ---------------- embedding ----------------
__global__ void embed_kernel(const int* __restrict__ tokens, const float* __restrict__ emb) {
    int gid = blockIdx.x * blockDim.x + threadIdx.x;
    int row = gid >> 6;
    int c4  = gid & 63;
    int t = row >> 7;
    int b = row & 127;
    int tok = tokens[b * T_LEN + t];
    const float4* e4 = reinterpret_cast<const float4*>(emb);
    float4*       x4 = reinterpret_cast<float4*>(g_x);
    x4[(size_t)row * 64 + c4] = e4[(size_t)tok * 64 + c4];
}

// ---------------- input projection GEMM (unchanged: 520us/layer, fma 62%) ----------------
__global__ __launch_bounds__(256) void proj_kernel(const float* __restrict__ W,
                                                   const float* __restrict__ bias) {
    __shared__ float As[16][128];
    __shared__ float Bs[16][128];
    int m0 = blockIdx.x * 128;
    int n0 = blockIdx.y * 128;
    int tid = threadIdx.x;
    int tx = tid & 15, ty = tid >> 4;
    float acc[8][8] = {};

    for (int k0 = 0; k0 < 256; k0 += 16) {
        #pragma unroll
        for (int i = 0; i < 2; i++) {               // A tile: transposed store
            int fid = tid + i * 256;
            int m   = fid >> 2;
            int kv  = fid & 3;
            float4 v = *reinterpret_cast<const float4*>(
                &g_x[(size_t)(m0 + m) * 256 + k0 + kv * 4]);
            As[kv * 4 + 0][m] = v.x; As[kv * 4 + 1][m] = v.y;
            As[kv * 4 + 2][m] = v.z; As[kv * 4 + 3][m] = v.w;
        }
        #pragma unroll
        for (int i = 0; i < 2; i++) {               // B tile: direct copy
            int fid = tid + i * 256;
            int kr  = fid >> 5;
            int nc  = fid & 31;
            *reinterpret_cast<float4*>(&Bs[kr][nc * 4]) =
                *reinterpret_cast<const float4*>(&W[(size_t)(k0 + kr) * NG + n0 + nc * 4]);
        }
        __syncthreads();
        #pragma unroll
        for (int kk = 0; kk < 16; kk++) {
            float4 b0 = *reinterpret_cast<const float4*>(&Bs[kk][tx * 4]);
            float4 b1 = *reinterpret_cast<const float4*>(&Bs[kk][64 + tx * 4]);
            float a[8];
            #pragma unroll
            for (int i = 0; i < 8; i++) a[i] = As[kk][ty * 8 + i];
            #pragma unroll
            for (int i = 0; i < 8; i++) {
                acc[i][0] = fmaf(a[i], b0.x, acc[i][0]);
                acc[i][1] = fmaf(a[i], b0.y, acc[i][1]);
                acc[i][2] = fmaf(a[i], b0.z, acc[i][2]);
                acc[i][3] = fmaf(a[i], b0.w, acc[i][3]);
                acc[i][4] = fmaf(a[i], b1.x, acc[i][4]);
                acc[i][5] = fmaf(a[i], b1.y, acc[i][5]);
                acc[i][6] = fmaf(a[i], b1.z, acc[i][6]);
                acc[i][7] = fmaf(a[i], b1.w, acc[i][7]);
            }
        }
        __syncthreads();
    }
    {
        int nA = n0 + tx * 4;
        int nB = n0 + 64 + tx * 4;
        float4 biasA = *reinterpret_cast<const float4*>(&bias[nA]);
        float4 biasB = *reinterpret_cast<const float4*>(&bias[nB]);
        #pragma unroll
        for (int i = 0; i < 8; i++) {
            size_t m = (size_t)(m0 + ty * 8 + i);
            float4 oA = make_float4(acc[i][0] + biasA.x, acc[i][1] + biasA.y,
                                    acc[i][2] + biasA.z, acc[i][3] + biasA.w);
            float4 oB = make_float4(acc[i][4] + biasB.x, acc[i][5] + biasB.y,
                                    acc[i][6] + biasB.z, acc[i][7] + biasB.w);
            *reinterpret_cast<float4*>(&g_xp[m * NG + nA]) = oA;
            *reinterpret_cast<float4*>(&g_xp[m * NG + nB]) = oB;
        }
    }
}

// ---------------- recurrent scan ----------------
// grid (32, 4): blockIdx.x = column-group (8 hidden units), blockIdx.y = batch-group (32 rows).
// GEMM phase: 256 threads = 64 positions (8 row-groups x 8 units) x 4 K-slices.
// h exchange through g_x[t]. ORDERING: every thread's g_x store precedes the
// pre-release __syncthreads(), so tid0's red.release publishes them (CG pattern).
extern __shared__ float smem[];
__global__ __launch_bounds__(256) void scan_kernel(const float* __restrict__ Wh,
                                                   const float* __restrict__ bh,
                                                   int layer) {
    float* Wh_s = smem;                            // [24 cols][WHS], col = gate*8 + j
    float* h_s  = smem + 24 * WHS;                 // skewed [32 rows], HROW(r) base
    float* red  = smem + 24 * WHS + 32 * HSS + 32; // [4 ks][64 p][12]
    int cg = blockIdx.x;
    int bg = blockIdx.y;
    int tid = threadIdx.x;
    int u0 = cg * 8;
    int b0 = bg * 32;
    unsigned* bar = g_bar + (layer * T_LEN) * 4 + bg;

    // GEMM-phase decode
    int ks  = tid >> 6;            // 0..3  K-slice
    int pos = tid & 63;            // 0..63
    int ty2 = pos >> 3;            // row-group 0..7 (rows ty2*4..+3)
    int txg = pos & 7;             // unit 0..7

    // Epilogue decode
    int er = tid >> 3;             // row 0..31
    int ej = tid & 7;              // unit 0..7
    int ep = (er >> 2) * 8 + ej;
    int erp = er & 3;

    // one-time Wh slice load
    for (int idx = tid; idx < 24 * 256; idx += 256) {
        int col  = idx >> 8;
        int k    = idx & 255;
        int gate = col >> 3;
        int j    = col & 7;
        Wh_s[col * WHS + k] = Wh[(size_t)k * NG + gate * 256 + u0 + j];
    }
    for (int i = tid; i < 32 * HSS + 32; i += 256) h_s[i] = 0.f;

    float bhz = bh[0 * 256 + u0 + ej];
    float bhr = bh[1 * 256 + u0 + ej];
    float bhh = bh[2 * 256 + u0 + ej];

    const float4* wz4 = reinterpret_cast<const float4*>(&Wh_s[(0 * 8 + txg) * WHS + ks * 64]);
    const float4* wr4 = reinterpret_cast<const float4*>(&Wh_s[(1 * 8 + txg) * WHS + ks * 64]);
    const float4* wh4 = reinterpret_cast<const float4*>(&Wh_s[(2 * 8 + txg) * WHS + ks * 64]);
    const float4* h0_4 = reinterpret_cast<const float4*>(h_s + HROW(ty2 * 4 + 0)) + ks * 16;
    const float4* h1_4 = reinterpret_cast<const float4*>(h_s + HROW(ty2 * 4 + 1)) + ks * 16;
    const float4* h2_4 = reinterpret_cast<const float4*>(h_s + HROW(ty2 * 4 + 2)) + ks * 16;
    const float4* h3_4 = reinterpret_cast<const float4*>(h_s + HROW(ty2 * 4 + 3)) + ks * 16;
    float* myred = &red[(ks * 64 + pos) * 12];

    int bglob = b0 + er;
    int u = u0 + ej;
    float hprev = 0.f;

    // prologue: xp(t=0)
    size_t xb0 = (size_t)bglob * NG;
    float xz = __ldcs(&g_xp[xb0 + u]);
    float xr = __ldcs(&g_xp[xb0 + 256 + u]);
    float xh = __ldcs(&g_xp[xb0 + 512 + u]);
    __syncthreads();

    for (int t = 0; t < T_LEN; t++) {
        // prefetch xp(t+1)
        float nxz = 0.f, nxr = 0.f, nxh = 0.f;
        if (t + 1 < T_LEN) {
            size_t xb = ((size_t)(t + 1) * B_SZ + bglob) * NG;
            nxz = __ldcs(&g_xp[xb + u]);
            nxr = __ldcs(&g_xp[xb + 256 + u]);
            nxh = __ldcs(&g_xp[xb + 512 + u]);
        }

        // ---- GEMM phase: acc[4 rows][3 gates] over K-slice of 64 ----
        float az0=0,az1=0,az2=0,az3=0, ar0=0,ar1=0,ar2=0,ar3=0, ah0=0,ah1=0,ah2=0,ah3=0;
        #pragma unroll 4
        for (int k4 = 0; k4 < 16; k4++) {
            float4 w_z = wz4[k4], w_r = wr4[k4], w_h = wh4[k4];
            float4 v0 = h0_4[k4], v1 = h1_4[k4], v2 = h2_4[k4], v3 = h3_4[k4];
            az0 = fmaf(v0.x,w_z.x,az0); az0 = fmaf(v0.y,w_z.y,az0); az0 = fmaf(v0.z,w_z.z,az0); az0 = fmaf(v0.w,w_z.w,az0);
            az1 = fmaf(v1.x,w_z.x,az1); az1 = fmaf(v1.y,w_z.y,az1); az1 = fmaf(v1.z,w_z.z,az1); az1 = fmaf(v1.w,w_z.w,az1);
            az2 = fmaf(v2.x,w_z.x,az2); az2 = fmaf(v2.y,w_z.y,az2); az2 = fmaf(v2.z,w_z.z,az2); az2 = fmaf(v2.w,w_z.w,az2);
            az3 = fmaf(v3.x,w_z.x,az3); az3 = fmaf(v3.y,w_z.y,az3); az3 = fmaf(v3.z,w_z.z,az3); az3 = fmaf(v3.w,w_z.w,az3);
            ar0 = fmaf(v0.x,w_r.x,ar0); ar0 = fmaf(v0.y,w_r.y,ar0); ar0 = fmaf(v0.z,w_r.z,ar0); ar0 = fmaf(v0.w,w_r.w,ar0);
            ar1 = fmaf(v1.x,w_r.x,ar1); ar1 = fmaf(v1.y,w_r.y,ar1); ar1 = fmaf(v1.z,w_r.z,ar1); ar1 = fmaf(v1.w,w_r.w,ar1);
            ar2 = fmaf(v2.x,w_r.x,ar2); ar2 = fmaf(v2.y,w_r.y,ar2); ar2 = fmaf(v2.z,w_r.z,ar2); ar2 = fmaf(v2.w,w_r.w,ar2);
            ar3 = fmaf(v3.x,w_r.x,ar3); ar3 = fmaf(v3.y,w_r.y,ar3); ar3 = fmaf(v3.z,w_r.z,ar3); ar3 = fmaf(v3.w,w_r.w,ar3);
            ah0 = fmaf(v0.x,w_h.x,ah0); ah0 = fmaf(v0.y,w_h.y,ah0); ah0 = fmaf(v0.z,w_h.z,ah0); ah0 = fmaf(v0.w,w_h.w,ah0);
            ah1 = fmaf(v1.x,w_h.x,ah1); ah1 = fmaf(v1.y,w_h.y,ah1); ah1 = fmaf(v1.z,w_h.z,ah1); ah1 = fmaf(v1.w,w_h.w,ah1);
            ah2 = fmaf(v2.x,w_h.x,ah2); ah2 = fmaf(v2.y,w_h.y,ah2); ah2 = fmaf(v2.z,w_h.z,ah2); ah2 = fmaf(v2.w,w_h.w,ah2);
            ah3 = fmaf(v3.x,w_h.x,ah3); ah3 = fmaf(v3.y,w_h.y,ah3); ah3 = fmaf(v3.z,w_h.z,ah3); ah3 = fmaf(v3.w,w_h.w,ah3);
        }
        {
            float4 s0 = make_float4(az0, ar0, ah0, az1);
            float4 s1 = make_float4(ar1, ah1, az2, ar2);
            float4 s2 = make_float4(ah2, az3, ar3, ah3);
            float4* r4 = reinterpret_cast<float4*>(myred);
            r4[0] = s0; r4[1] = s1; r4[2] = s2;
        }
        __syncthreads();

        // ---- epilogue ----
        float az = bhz, ar = bhr, ah = bhh;
        #pragma unroll
        for (int s = 0; s < 4; s++) {
            const float* rr = &red[(s * 64 + ep) * 12 + erp * 3];
            az += rr[0]; ar += rr[1]; ah += rr[2];
        }

        float z  = __fdividef(1.f, 1.f + __expf(-(xz + az)));
        float r  = __fdividef(1.f, 1.f + __expf(-(xr + ar)));
        float e2 = __expf(2.f * (xh + r * ah));
        float cand = 1.f - __fdividef(2.f, e2 + 1.f);     // tanh
        float hn = z * hprev + (1.f - z) * cand;
        hprev = hn;

        // h-exchange + next-layer store: MUST precede the pre-release barrier
        __stcg(&g_x[((size_t)t * B_SZ + bglob) * 256 + u], hn);

        __syncthreads();   // red reads done + ALL g_x stores ordered before release

        if (t < T_LEN - 1) {
            if (tid == 0) {
                unsigned* a = &bar[t * 4];
                asm volatile("red.release.gpu.global.add.u32 [%0], %1;"
                             :: "l"(a), "r"(1u) : "memory");
                unsigned v;
                do {
                    asm volatile("ld.acquire.gpu.global.u32 %0, [%1];"
                                 : "=r"(v) : "l"(a) : "memory");
                } while (v < BG_CTAS);
            }
            __syncthreads();
            // reload 32x256 h tile from g_x[t] (L2) into skewed h_s
            const float4* hg = reinterpret_cast<const float4*>(&g_x[((size_t)t * B_SZ + b0) * 256]);
            #pragma unroll
            for (int i = 0; i < 8; i++) {
                int idx = tid + i * 256;
                float4 v = __ldcg(&hg[idx]);
                int row = idx >> 6, c4 = idx & 63;
                reinterpret_cast<float4*>(h_s + HROW(row))[c4] = v;
            }
            __syncthreads();
        }
        xz = nxz; xr = nxr; xh = nxh;
    }
}

// ---------------- classifier head ----------------
__global__ void dense_kernel(const float* __restrict__ Wd1, const float* __restrict__ bd1,
                             const float* __restrict__ Wd2, const float* __restrict__ bd2,
                             float* __restrict__ out) {
    __shared__ float xs[256];
    __shared__ float red[256];
    int b = blockIdx.x;
    int j = threadIdx.x;
    xs[j] = g_x[((size_t)(T_LEN - 1) * B_SZ + b) * 256 + j];
    __syncthreads();
    float acc = bd1[j];
    #pragma unroll 8
    for (int k = 0; k < 256; k++) acc = fmaf(xs[k], Wd1[k * 256 + j], acc);
    float h1 = acc > 0.f ? acc : 0.f;
    red[j] = h1 * Wd2[j];
    __syncthreads();
    for (int s = 128; s > 0; s >>= 1) {
        if (j < s) red[j] += red[j + s];
        __syncthreads();
    }
    if (j == 0) out[b] = 1.f / (1.f + expf(-(red[0] + bd2[0])));
}

// ---------------- launch ----------------
extern "C" void kernel_launch(void* const* d_in, const int* in_sizes, int n_in,
                              void* d_out, int out_size) {
    const int*   tokens = (const int*)  d_in[0];
    const float* emb    = (const float*)d_in[1];
    float* out = (float*)d_out;

    void* bar_addr; cudaGetSymbolAddress(&bar_addr, g_bar);

    const int scan_smem = (24 * WHS + 32 * HSS + 32 + 4 * 64 * 12) * (int)sizeof(float); // 70656 B
    cudaFuncSetAttribute(scan_kernel, cudaFuncAttributeMaxDynamicSharedMemorySize, scan_smem);

    cudaMemsetAsync(bar_addr, 0, sizeof(unsigned) * 4 * T_LEN * 4);

    embed_kernel<<<16384, 256>>>(tokens, emb);

    for (int l = 0; l < 4; l++) {
        const float* Wx = (const float*)d_in[2 + 4 * l];
        const float* Wh = (const float*)d_in[3 + 4 * l];
        const float* bx = (const float*)d_in[4 + 4 * l];
        const float* bh = (const float*)d_in[5 + 4 * l];

        dim3 pgrid(512, 6);
        proj_kernel<<<pgrid, 256>>>(Wx, bx);

        scan_kernel<<<dim3(32, 4), 256, scan_smem>>>(Wh, bh, l);
    }

    dense_kernel<<<128, 256>>>((const float*)d_in[18], (const float*)d_in[19],
                               (const float*)d_in[20], (const float*)d_in[21], out);
}